// round 9
// baseline (speedup 1.0000x reference)
#include <cuda_runtime.h>
#include <cstdint>
#include <math.h>

#define T_TOK 8192
#define DIM   1024
#define FF    4096
#define NE    8
#define SLOTS (T_TOK * 2)

// ---------------- device scratch ----------------
__device__ int   g_offsets[NE + 1];
__device__ int   g_tok_e[SLOTS];
__device__ float g_tok_w[SLOTS];
__device__ int   g_tok[SLOTS];                  // slot -> token
__device__ int   g_slot[SLOTS];                 // token*2+k -> slot
__device__ float g_H[(size_t)SLOTS * FF];       // SwiGLU intermediate (tf32-rounded)
__device__ float g_R[(size_t)SLOTS * DIM];      // down-proj per slot (fp32)
__device__ float g_xr[(size_t)T_TOK * DIM];     // tf32-rounded x
__device__ float g_w1r[(size_t)NE * DIM * FF];
__device__ float g_w3r[(size_t)NE * DIM * FF];
__device__ float g_w2r[(size_t)NE * FF * DIM];

// ---------------- helpers ----------------
__device__ __forceinline__ uint32_t smem_u32(const void* p) {
    uint32_t a;
    asm("{ .reg .u64 t; cvta.to.shared.u64 t, %1; cvt.u32.u64 %0, t; }" : "=r"(a) : "l"(p));
    return a;
}
__device__ __forceinline__ uint32_t f2tf32(float f) {
    uint32_t r; asm("cvt.rna.tf32.f32 %0, %1;" : "=r"(r) : "f"(f)); return r;
}
#define CP_ASYNC16(dst, src) \
    asm volatile("cp.async.cg.shared.global [%0], [%1], 16;" :: "r"(dst), "l"(src) : "memory")
#define CP_COMMIT() asm volatile("cp.async.commit_group;" ::: "memory")
#define CP_WAIT(n)  asm volatile("cp.async.wait_group %0;" :: "n"(n) : "memory")

__device__ __forceinline__ void ldsm_x4(uint32_t* r, uint32_t addr) {
    asm volatile("ldmatrix.sync.aligned.m8n8.x4.shared.b16 {%0,%1,%2,%3}, [%4];"
        : "=r"(r[0]), "=r"(r[1]), "=r"(r[2]), "=r"(r[3]) : "r"(addr));
}
__device__ __forceinline__ void mma_tf32(float* c, const uint32_t* a, uint32_t b0, uint32_t b1) {
    asm volatile(
        "mma.sync.aligned.m16n8k8.row.col.f32.tf32.tf32.f32 "
        "{%0,%1,%2,%3}, {%4,%5,%6,%7}, {%8,%9}, {%0,%1,%2,%3};\n"
        : "+f"(c[0]), "+f"(c[1]), "+f"(c[2]), "+f"(c[3])
        : "r"(a[0]), "r"(a[1]), "r"(a[2]), "r"(a[3]), "r"(b0), "r"(b1));
}
__device__ __forceinline__ float silu_f(float g) { return g / (1.0f + __expf(-g)); }

// ---------------- launch #1: round all 3 weight tensors ----------------
__global__ void moe_round_w(const float4* __restrict__ w1, float4* __restrict__ d1,
                            const float4* __restrict__ w3, float4* __restrict__ d3,
                            const float4* __restrict__ w2, float4* __restrict__ d2, int n4) {
    const float4* s; float4* d;
    if (blockIdx.y == 0)      { s = w1; d = d1; }
    else if (blockIdx.y == 1) { s = w3; d = d3; }
    else                      { s = w2; d = d2; }
    int i = blockIdx.x * blockDim.x + threadIdx.x;
    if (i >= n4) return;
    float4 v = s[i], o;
    o.x = __uint_as_float(f2tf32(v.x));
    o.y = __uint_as_float(f2tf32(v.y));
    o.z = __uint_as_float(f2tf32(v.z));
    o.w = __uint_as_float(f2tf32(v.w));
    d[i] = o;
}

// ---------------- launch #2: gating + x rounding (fused) ----------------
__global__ void moe_gate_kernel(const float* __restrict__ x, const float* __restrict__ gw) {
    int warp = (blockIdx.x * blockDim.x + threadIdx.x) >> 5;
    int lane = threadIdx.x & 31;
    if (warp >= T_TOK) return;
    const float* xr = x + (size_t)warp * DIM;
    float* xo = g_xr + (size_t)warp * DIM;
    float acc[NE];
#pragma unroll
    for (int e = 0; e < NE; e++) acc[e] = 0.f;
    for (int d = lane; d < DIM; d += 32) {
        float xv = xr[d];
        xo[d] = __uint_as_float(f2tf32(xv));       // fused tf32 rounding of x
        const float* g = gw + d * NE;
#pragma unroll
        for (int e = 0; e < NE; e++) acc[e] += xv * g[e];
    }
#pragma unroll
    for (int e = 0; e < NE; e++)
#pragma unroll
        for (int o = 16; o > 0; o >>= 1) acc[e] += __shfl_xor_sync(0xffffffffu, acc[e], o);
    if (lane == 0) {
        int i1 = 0; float v1 = acc[0];
#pragma unroll
        for (int e = 1; e < NE; e++) if (acc[e] > v1) { v1 = acc[e]; i1 = e; }
        int i2 = -1; float v2 = -INFINITY;
#pragma unroll
        for (int e = 0; e < NE; e++) if (e != i1 && acc[e] > v2) { v2 = acc[e]; i2 = e; }
        float e2 = expf(v2 - v1);
        float inv = 1.0f / (1.0f + e2);
        g_tok_e[warp * 2 + 0] = i1;
        g_tok_e[warp * 2 + 1] = i2;
        g_tok_w[warp * 2 + 0] = inv;
        g_tok_w[warp * 2 + 1] = e2 * inv;
    }
}

// ---------------- launch #3: count + offsets + scatter (one block) ----------------
__global__ void moe_sched_kernel() {
    __shared__ int sc[NE];
    int tid = threadIdx.x;
    if (tid < NE) sc[tid] = 0;
    __syncthreads();
    for (int i = tid; i < SLOTS; i += blockDim.x)
        atomicAdd(&sc[g_tok_e[i]], 1);
    __syncthreads();
    if (tid == 0) {
        int o = 0;
        g_offsets[0] = 0;
#pragma unroll
        for (int e = 0; e < NE; e++) {
            int c = sc[e];
            o += c;
            g_offsets[e + 1] = o;
            sc[e] = o - c;   // cursor = start offset
        }
    }
    __syncthreads();
    for (int i = tid; i < SLOTS; i += blockDim.x) {
        int e = g_tok_e[i];
        int slot = atomicAdd(&sc[e], 1);
        g_tok[slot] = i >> 1;
        g_slot[i] = slot;
    }
}

// ---------------- GEMM config ----------------
// BK=32. A smem row: 32k + 4 pad = 36 words (144B).
#define A_BYTES  18432                    // 128 * 144
#define SB1_W    136                      // 128n + 8 pad words
#define B1_BYTES 17408                    // 32 * 544
#define STG1     (A_BYTES + 2 * B1_BYTES) // 53248
#define SB2_W    264                      // 256n + 8 pad words
#define B2_BYTES 33792                    // 32 * 1056
#define STG2     (A_BYTES + B2_BYTES)     // 52224

// ---------------- launch #4: GEMM1 x@w1,x@w3 -> SwiGLU -> g_H ----------------
// 256 threads, 8 warps (2m x 4n), warp tile 64M x 32N per mat; CTA 128M x 128N/mat.
__device__ __forceinline__ void fill1(uint32_t sb, int kc, int ncol0,
                                      const float* __restrict__ w1e,
                                      const float* __restrict__ w3e,
                                      const int* sTok, int tid) {
    int k0 = kc * 32;
#pragma unroll
    for (int i = 0; i < 4; i++) {
        int c = tid + i * 256;
        int r = c >> 3, c4 = c & 7;
        const float* src = g_xr + (size_t)sTok[r] * DIM + k0 + c4 * 4;
        CP_ASYNC16(sb + r * 144 + c4 * 16, src);
    }
    const float* w = (tid < 128) ? w1e : w3e;
    uint32_t boff = sb + ((tid < 128) ? A_BYTES : (A_BYTES + B1_BYTES));
    int t = tid & 127;
#pragma unroll
    for (int i = 0; i < 8; i++) {
        int c = t + i * 128;
        int kr = c >> 5, n4 = c & 31;
        const float* src = w + (size_t)(k0 + kr) * FF + ncol0 + n4 * 4;
        CP_ASYNC16(boff + kr * 544 + n4 * 16, src);
    }
}

__global__ __launch_bounds__(256, 1)
void moe_gemm1(const float* __restrict__ w1r, const float* __restrict__ w3r) {
    int bid = blockIdx.x;
    int mt = bid & 63, nt = (bid >> 6) & 31, e = bid >> 11;
    int row0 = g_offsets[e] + mt * 128;
    int row_end = g_offsets[e + 1];
    if (row0 >= row_end) return;
    int rows = min(128, row_end - row0);

    extern __shared__ char dsm[];
    __shared__ int sTok[128];

    int tid = threadIdx.x;
    if (tid < 128) sTok[tid] = g_tok[row0 + ((tid < rows) ? tid : 0)];
    __syncthreads();

    uint32_t smem0 = smem_u32(dsm);
    const float* w1e = w1r + (size_t)e * DIM * FF;
    const float* w3e = w3r + (size_t)e * DIM * FF;
    int ncol0 = nt * 128;

    int warp = tid >> 5, lane = tid & 31;
    int wm = warp & 1, wn = warp >> 1;
    int mrow = wm * 64, ncol = wn * 32;
    int grp = lane >> 2, tig = lane & 3;
    int lm = lane >> 3, lr = lane & 7;
    uint32_t aOff = (uint32_t)(((lm & 1) * 8 + lr) * 144 + (lm >> 1) * 16);

    float accG[4][4][4], accV[4][4][4];
#pragma unroll
    for (int mi = 0; mi < 4; mi++)
#pragma unroll
        for (int ni = 0; ni < 4; ni++)
#pragma unroll
            for (int q = 0; q < 4; q++) { accG[mi][ni][q] = 0.f; accV[mi][ni][q] = 0.f; }

    fill1(smem0 + 0 * STG1, 0, ncol0, w1e, w3e, sTok, tid); CP_COMMIT();
    fill1(smem0 + 1 * STG1, 1, ncol0, w1e, w3e, sTok, tid); CP_COMMIT();

    const int KT = DIM / 32;   // 32
    for (int kt = 0; kt < KT; kt++) {
        CP_WAIT(1);
        __syncthreads();
        if (kt + 2 < KT)
            fill1(smem0 + ((kt + 2) % 3) * STG1, kt + 2, ncol0, w1e, w3e, sTok, tid);
        CP_COMMIT();

        uint32_t stOff = (uint32_t)((kt % 3) * STG1);
        const uint32_t* sB1 = (const uint32_t*)(dsm + stOff + A_BYTES);
        const uint32_t* sB3 = (const uint32_t*)(dsm + stOff + A_BYTES + B1_BYTES);
        uint32_t aBase = smem0 + stOff + mrow * 144 + aOff;
#pragma unroll
        for (int kk = 0; kk < 32; kk += 8) {
            uint32_t a[4][4];
#pragma unroll
            for (int mi = 0; mi < 4; mi++)
                ldsm_x4(a[mi], aBase + mi * 16 * 144 + kk * 4);
#pragma unroll
            for (int ni = 0; ni < 4; ni++) {
                int kb = (kk + tig) * SB1_W + ncol + ni * 8 + grp;
                uint32_t b10 = sB1[kb], b11 = sB1[kb + 4 * SB1_W];
                uint32_t b30 = sB3[kb], b31 = sB3[kb + 4 * SB1_W];
#pragma unroll
                for (int mi = 0; mi < 4; mi++) {
                    mma_tf32(accG[mi][ni], a[mi], b10, b11);
                    mma_tf32(accV[mi][ni], a[mi], b30, b31);
                }
            }
        }
    }

    // epilogue: SwiGLU, round to tf32, store to g_H
#pragma unroll
    for (int mi = 0; mi < 4; mi++) {
#pragma unroll
        for (int ni = 0; ni < 4; ni++) {
            int r = mrow + mi * 16 + grp;
            int c = ncol + ni * 8 + tig * 2;
            size_t gc = (size_t)ncol0 + c;
            const float* g = accG[mi][ni];
            const float* v = accV[mi][ni];
            if (r < rows) {
                float h0 = silu_f(g[0]) * v[0];
                float h1 = silu_f(g[1]) * v[1];
                *(float2*)&g_H[(size_t)(row0 + r) * FF + gc] =
                    make_float2(__uint_as_float(f2tf32(h0)), __uint_as_float(f2tf32(h1)));
            }
            int r2 = r + 8;
            if (r2 < rows) {
                float h2 = silu_f(g[2]) * v[2];
                float h3 = silu_f(g[3]) * v[3];
                *(float2*)&g_H[(size_t)(row0 + r2) * FF + gc] =
                    make_float2(__uint_as_float(f2tf32(h2)), __uint_as_float(f2tf32(h3)));
            }
        }
    }
}

// ---------------- launch #5: GEMM2 g_H @ w2 -> g_R ----------------
// 256 threads, 8 warps (2m x 4n), warp tile 64M x 64N; CTA 128M x 256N.
__device__ __forceinline__ void fill2(uint32_t sb, int kc, int ncol0,
                                      const float* __restrict__ w2e,
                                      int row0, int rows, int tid) {
    int k0 = kc * 32;
#pragma unroll
    for (int i = 0; i < 4; i++) {
        int c = tid + i * 256;
        int r = c >> 3, c4 = c & 7;
        int rsrc = row0 + ((r < rows) ? r : 0);
        const float* src = g_H + (size_t)rsrc * FF + k0 + c4 * 4;
        CP_ASYNC16(sb + r * 144 + c4 * 16, src);
    }
#pragma unroll
    for (int i = 0; i < 8; i++) {
        int c = tid + i * 256;
        int kr = c >> 6, n4 = c & 63;
        const float* src = w2e + (size_t)(k0 + kr) * DIM + ncol0 + n4 * 4;
        CP_ASYNC16(sb + A_BYTES + kr * 1056 + n4 * 16, src);
    }
}

__global__ __launch_bounds__(256, 1)
void moe_gemm2(const float* __restrict__ w2r) {
    int bid = blockIdx.x;
    int nt = bid & 3, mt = (bid >> 2) & 63, e = bid >> 8;
    int row0 = g_offsets[e] + mt * 128;
    int row_end = g_offsets[e + 1];
    if (row0 >= row_end) return;
    int rows = min(128, row_end - row0);

    extern __shared__ char dsm[];
    int tid = threadIdx.x;
    uint32_t smem0 = smem_u32(dsm);
    const float* w2e = w2r + (size_t)e * FF * DIM;
    int ncol0 = nt * 256;

    int warp = tid >> 5, lane = tid & 31;
    int wm = warp & 1, wn = warp >> 1;
    int mrow = wm * 64, ncol = wn * 64;
    int grp = lane >> 2, tig = lane & 3;
    int lm = lane >> 3, lr = lane & 7;
    uint32_t aOff = (uint32_t)(((lm & 1) * 8 + lr) * 144 + (lm >> 1) * 16);

    float accC[4][8][4];
#pragma unroll
    for (int mi = 0; mi < 4; mi++)
#pragma unroll
        for (int ni = 0; ni < 8; ni++)
#pragma unroll
            for (int q = 0; q < 4; q++) accC[mi][ni][q] = 0.f;

    fill2(smem0 + 0 * STG2, 0, ncol0, w2e, row0, rows, tid); CP_COMMIT();
    fill2(smem0 + 1 * STG2, 1, ncol0, w2e, row0, rows, tid); CP_COMMIT();

    const int KT = FF / 32;   // 128
    for (int kt = 0; kt < KT; kt++) {
        CP_WAIT(1);
        __syncthreads();
        if (kt + 2 < KT)
            fill2(smem0 + ((kt + 2) % 3) * STG2, kt + 2, ncol0, w2e, row0, rows, tid);
        CP_COMMIT();

        uint32_t stOff = (uint32_t)((kt % 3) * STG2);
        const uint32_t* sB = (const uint32_t*)(dsm + stOff + A_BYTES);
        uint32_t aBase = smem0 + stOff + mrow * 144 + aOff;
#pragma unroll
        for (int kk = 0; kk < 32; kk += 8) {
            uint32_t a[4][4];
#pragma unroll
            for (int mi = 0; mi < 4; mi++)
                ldsm_x4(a[mi], aBase + mi * 16 * 144 + kk * 4);
#pragma unroll
            for (int ni = 0; ni < 8; ni++) {
                int kb = (kk + tig) * SB2_W + ncol + ni * 8 + grp;
                uint32_t b0 = sB[kb], b1 = sB[kb + 4 * SB2_W];
#pragma unroll
                for (int mi = 0; mi < 4; mi++)
                    mma_tf32(accC[mi][ni], a[mi], b0, b1);
            }
        }
    }

    // epilogue: raw fp32 per-slot rows
#pragma unroll
    for (int mi = 0; mi < 4; mi++) {
#pragma unroll
        for (int ni = 0; ni < 8; ni++) {
            int r = mrow + mi * 16 + grp;
            int c = ncol + ni * 8 + tig * 2;
            size_t gc = (size_t)ncol0 + c;
            const float* a = accC[mi][ni];
            if (r < rows)
                *(float2*)&g_R[(size_t)(row0 + r) * DIM + gc] = make_float2(a[0], a[1]);
            int r2 = r + 8;
            if (r2 < rows)
                *(float2*)&g_R[(size_t)(row0 + r2) * DIM + gc] = make_float2(a[2], a[3]);
        }
    }
}

// ---------------- launch #6: combine out[t] = w0*R[s0] + w1*R[s1] ----------------
__global__ void moe_combine_kernel(float4* __restrict__ out4) {
    const int n = T_TOK * (DIM / 4);
    int i = blockIdx.x * blockDim.x + threadIdx.x;
    if (i >= n) return;
    int t = i >> 8;
    int c = i & 255;
    int s0 = g_slot[t * 2 + 0], s1 = g_slot[t * 2 + 1];
    float w0 = g_tok_w[t * 2 + 0], w1 = g_tok_w[t * 2 + 1];
    const float4* R4 = (const float4*)g_R;
    float4 a = R4[(size_t)s0 * 256 + c];
    float4 b = R4[(size_t)s1 * 256 + c];
    float4 o;
    o.x = w0 * a.x + w1 * b.x;
    o.y = w0 * a.y + w1 * b.y;
    o.z = w0 * a.z + w1 * b.z;
    o.w = w0 * a.w + w1 * b.w;
    out4[i] = o;
}

// ---------------- launch ----------------
extern "C" void kernel_launch(void* const* d_in, const int* in_sizes, int n_in,
                              void* d_out, int out_size) {
    (void)in_sizes; (void)n_in; (void)out_size;
    const float* x  = (const float*)d_in[0];
    const float* gw = (const float*)d_in[1];
    const float* w1 = (const float*)d_in[2];
    const float* w3 = (const float*)d_in[3];
    const float* w2 = (const float*)d_in[4];
    float* out = (float*)d_out;

    float* d_w1r; cudaGetSymbolAddress((void**)&d_w1r, g_w1r);
    float* d_w3r; cudaGetSymbolAddress((void**)&d_w3r, g_w3r);
    float* d_w2r; cudaGetSymbolAddress((void**)&d_w2r, g_w2r);

    const int DYN1 = 3 * STG1;   // 159744
    const int DYN2 = 3 * STG2;   // 156672
    cudaFuncSetAttribute(moe_gemm1, cudaFuncAttributeMaxDynamicSharedMemorySize, DYN1);
    cudaFuncSetAttribute(moe_gemm2, cudaFuncAttributeMaxDynamicSharedMemorySize, DYN2);

    int nw = NE * DIM * FF / 4;
    // #1 weights round
    dim3 gw3((nw + 255) / 256, 3);
    moe_round_w<<<gw3, 256>>>((const float4*)w1, (float4*)d_w1r,
                              (const float4*)w3, (float4*)d_w3r,
                              (const float4*)w2, (float4*)d_w2r, nw);
    // #2 gate + x round (fused)
    moe_gate_kernel<<<T_TOK / 8, 256>>>(x, gw);
    // #3 count + offsets + scatter (fused, one block)
    moe_sched_kernel<<<1, 1024>>>();
    // #4 GEMM1: e(8) x nt(32) x mt(64), mt fastest  <- ncu profiles this launch
    moe_gemm1<<<8 * 32 * 64, 256, DYN1>>>(d_w1r, d_w3r);
    // #5 GEMM2: e(8) x mt(64) x nt(4), nt fastest
    moe_gemm2<<<8 * 64 * 4, 256, DYN2>>>(d_w2r);
    // #6 combine
    moe_combine_kernel<<<(T_TOK * DIM / 4 + 255) / 256, 256>>>((float4*)out);
}

// round 12
// speedup vs baseline: 1.6856x; 1.6856x over previous
#include <cuda_runtime.h>
#include <cuda_fp16.h>
#include <cstdint>
#include <math.h>

#define T_TOK 8192
#define DIM   1024
#define FF    4096
#define NE    8
#define SLOTS (T_TOK * 2)

// ---------------- device scratch ----------------
__device__ int    g_offsets[NE + 1];
__device__ int    g_tok_e[SLOTS];
__device__ float  g_tok_w[SLOTS];
__device__ int    g_tok[SLOTS];                   // slot -> token
__device__ int    g_slot[SLOTS];                  // token*2+k -> slot
__device__ __half g_Hh[(size_t)SLOTS * FF];       // SwiGLU intermediate (fp16)
__device__ float  g_R[(size_t)SLOTS * DIM];       // down-proj per slot (fp32)
__device__ __half g_xh[(size_t)T_TOK * DIM];      // fp16 x
__device__ __half g_w1h[(size_t)NE * DIM * FF];
__device__ __half g_w3h[(size_t)NE * DIM * FF];
__device__ __half g_w2h[(size_t)NE * FF * DIM];

// ---------------- helpers ----------------
__device__ __forceinline__ uint32_t smem_u32(const void* p) {
    uint32_t a;
    asm("{ .reg .u64 t; cvta.to.shared.u64 t, %1; cvt.u32.u64 %0, t; }" : "=r"(a) : "l"(p));
    return a;
}
#define CP_ASYNC16(dst, src) \
    asm volatile("cp.async.cg.shared.global [%0], [%1], 16;" :: "r"(dst), "l"(src) : "memory")
#define CP_COMMIT() asm volatile("cp.async.commit_group;" ::: "memory")
#define CP_WAIT(n)  asm volatile("cp.async.wait_group %0;" :: "n"(n) : "memory")

__device__ __forceinline__ void ldsm_x4(uint32_t* r, uint32_t addr) {
    asm volatile("ldmatrix.sync.aligned.m8n8.x4.shared.b16 {%0,%1,%2,%3}, [%4];"
        : "=r"(r[0]), "=r"(r[1]), "=r"(r[2]), "=r"(r[3]) : "r"(addr));
}
__device__ __forceinline__ void ldsm_x2t(uint32_t* r, uint32_t addr) {
    asm volatile("ldmatrix.sync.aligned.m8n8.x2.trans.shared.b16 {%0,%1}, [%2];"
        : "=r"(r[0]), "=r"(r[1]) : "r"(addr));
}
__device__ __forceinline__ void mma_f16(float* c, const uint32_t* a, uint32_t b0, uint32_t b1) {
    asm volatile(
        "mma.sync.aligned.m16n8k16.row.col.f32.f16.f16.f32 "
        "{%0,%1,%2,%3}, {%4,%5,%6,%7}, {%8,%9}, {%0,%1,%2,%3};\n"
        : "+f"(c[0]), "+f"(c[1]), "+f"(c[2]), "+f"(c[3])
        : "r"(a[0]), "r"(a[1]), "r"(a[2]), "r"(a[3]), "r"(b0), "r"(b1));
}
__device__ __forceinline__ float silu_f(float g) { return g / (1.0f + __expf(-g)); }

// ---------------- launch #1: convert 3 weight tensors fp32 -> fp16 ----------------
__global__ void moe_round_w(const float4* __restrict__ w1, __half2* __restrict__ d1,
                            const float4* __restrict__ w3, __half2* __restrict__ d3,
                            const float4* __restrict__ w2, __half2* __restrict__ d2, int n4) {
    const float4* s; __half2* d;
    if (blockIdx.y == 0)      { s = w1; d = d1; }
    else if (blockIdx.y == 1) { s = w3; d = d3; }
    else                      { s = w2; d = d2; }
    int i = blockIdx.x * blockDim.x + threadIdx.x;
    if (i >= n4) return;
    float4 v = s[i];
    d[(size_t)i * 2 + 0] = __floats2half2_rn(v.x, v.y);
    d[(size_t)i * 2 + 1] = __floats2half2_rn(v.z, v.w);
}

// ---------------- launch #2: gating + x fp16 conversion (fused) ----------------
__global__ void moe_gate_kernel(const float* __restrict__ x, const float* __restrict__ gw) {
    int warp = (blockIdx.x * blockDim.x + threadIdx.x) >> 5;
    int lane = threadIdx.x & 31;
    if (warp >= T_TOK) return;
    const float* xr = x + (size_t)warp * DIM;
    __half* xo = g_xh + (size_t)warp * DIM;
    float acc[NE];
#pragma unroll
    for (int e = 0; e < NE; e++) acc[e] = 0.f;
    for (int d = lane; d < DIM; d += 32) {
        float xv = xr[d];
        xo[d] = __float2half_rn(xv);
        const float* g = gw + d * NE;
#pragma unroll
        for (int e = 0; e < NE; e++) acc[e] += xv * g[e];
    }
#pragma unroll
    for (int e = 0; e < NE; e++)
#pragma unroll
        for (int o = 16; o > 0; o >>= 1) acc[e] += __shfl_xor_sync(0xffffffffu, acc[e], o);
    if (lane == 0) {
        int i1 = 0; float v1 = acc[0];
#pragma unroll
        for (int e = 1; e < NE; e++) if (acc[e] > v1) { v1 = acc[e]; i1 = e; }
        int i2 = -1; float v2 = -INFINITY;
#pragma unroll
        for (int e = 0; e < NE; e++) if (e != i1 && acc[e] > v2) { v2 = acc[e]; i2 = e; }
        float e2 = expf(v2 - v1);
        float inv = 1.0f / (1.0f + e2);
        g_tok_e[warp * 2 + 0] = i1;
        g_tok_e[warp * 2 + 1] = i2;
        g_tok_w[warp * 2 + 0] = inv;
        g_tok_w[warp * 2 + 1] = e2 * inv;
    }
}

// ---------------- launch #3: count + offsets + scatter (one block) ----------------
__global__ void moe_sched_kernel() {
    __shared__ int sc[NE];
    int tid = threadIdx.x;
    if (tid < NE) sc[tid] = 0;
    __syncthreads();
    for (int i = tid; i < SLOTS; i += blockDim.x)
        atomicAdd(&sc[g_tok_e[i]], 1);
    __syncthreads();
    if (tid == 0) {
        int o = 0;
        g_offsets[0] = 0;
#pragma unroll
        for (int e = 0; e < NE; e++) {
            int c = sc[e];
            o += c;
            g_offsets[e + 1] = o;
            sc[e] = o - c;
        }
    }
    __syncthreads();
    for (int i = tid; i < SLOTS; i += blockDim.x) {
        int e = g_tok_e[i];
        int slot = atomicAdd(&sc[e], 1);
        g_tok[slot] = i >> 1;
        g_slot[i] = slot;
    }
}

// ---------------- GEMM config (fp16, BK=64) ----------------
// A smem row: 64 halves + 8 pad = 144B (stride 36 words == 4 mod 32: ldmatrix conflict-free).
// B1 smem row: 128 halves + 8 pad = 272B (68 words == 4 mod 32).
// B2 smem row: 256 halves + 8 pad = 528B (132 words == 4 mod 32).
#define A_BYTES  18432                    // 128 * 144
#define B1_BYTES 17408                    // 64 * 272
#define STG1     (A_BYTES + 2 * B1_BYTES) // 53248
#define B2_BYTES 33792                    // 64 * 528
#define STG2     (A_BYTES + B2_BYTES)     // 52224

// ---------------- launch #4: GEMM1 x@w1,x@w3 -> SwiGLU -> g_Hh ----------------
// 256 threads, 8 warps (2m x 4n), warp tile 64M x 32N per mat; CTA 128M x 128N/mat.
__device__ __forceinline__ void fill1(uint32_t sb, int kc, int ncol0,
                                      const __half* __restrict__ w1e,
                                      const __half* __restrict__ w3e,
                                      const int* sTok, int tid) {
    int k0 = kc * 64;
#pragma unroll
    for (int i = 0; i < 4; i++) {
        int c = tid + i * 256;
        int r = c >> 3, c4 = c & 7;                      // 8 x 16B chunks per 64-half row
        const __half* src = g_xh + (size_t)sTok[r] * DIM + k0 + c4 * 8;
        CP_ASYNC16(sb + r * 144 + c4 * 16, src);
    }
    const __half* w = (tid < 128) ? w1e : w3e;
    uint32_t boff = sb + ((tid < 128) ? A_BYTES : (A_BYTES + B1_BYTES));
    int t = tid & 127;
#pragma unroll
    for (int i = 0; i < 8; i++) {
        int c = t + i * 128;
        int kr = c >> 4, n4 = c & 15;                    // 16 x 16B chunks per 128-half row
        const __half* src = w + (size_t)(k0 + kr) * FF + ncol0 + n4 * 8;
        CP_ASYNC16(boff + kr * 272 + n4 * 16, src);
    }
}

__global__ __launch_bounds__(256, 1)
void moe_gemm1(const __half* __restrict__ w1h, const __half* __restrict__ w3h) {
    int bid = blockIdx.x;
    int mt = bid & 63, nt = (bid >> 6) & 31, e = bid >> 11;
    int row0 = g_offsets[e] + mt * 128;
    int row_end = g_offsets[e + 1];
    if (row0 >= row_end) return;
    int rows = min(128, row_end - row0);

    extern __shared__ char dsm[];
    __shared__ int sTok[128];

    int tid = threadIdx.x;
    if (tid < 128) sTok[tid] = g_tok[row0 + ((tid < rows) ? tid : 0)];
    __syncthreads();

    uint32_t smem0 = smem_u32(dsm);
    const __half* w1e = w1h + (size_t)e * DIM * FF;
    const __half* w3e = w3h + (size_t)e * DIM * FF;
    int ncol0 = nt * 128;

    int warp = tid >> 5, lane = tid & 31;
    int wm = warp & 1, wn = warp >> 1;
    int mrow = wm * 64, ncol = wn * 32;
    int grp = lane >> 2, tig = lane & 3;
    int lm = lane >> 3, lr = lane & 7;
    uint32_t aOff = (uint32_t)(((lm & 1) * 8 + lr) * 144 + (lm >> 1) * 16);
    uint32_t bOff = (uint32_t)(((lm & 1) * 8 + lr) * 272 + ncol * 2);

    float accG[4][4][4], accV[4][4][4];
#pragma unroll
    for (int mi = 0; mi < 4; mi++)
#pragma unroll
        for (int ni = 0; ni < 4; ni++)
#pragma unroll
            for (int q = 0; q < 4; q++) { accG[mi][ni][q] = 0.f; accV[mi][ni][q] = 0.f; }

    fill1(smem0 + 0 * STG1, 0, ncol0, w1e, w3e, sTok, tid); CP_COMMIT();
    fill1(smem0 + 1 * STG1, 1, ncol0, w1e, w3e, sTok, tid); CP_COMMIT();

    const int KT = DIM / 64;   // 16
    for (int kt = 0; kt < KT; kt++) {
        CP_WAIT(1);
        __syncthreads();
        if (kt + 2 < KT)
            fill1(smem0 + ((kt + 2) % 3) * STG1, kt + 2, ncol0, w1e, w3e, sTok, tid);
        CP_COMMIT();

        uint32_t stOff = (uint32_t)((kt % 3) * STG1);
        uint32_t aBase = smem0 + stOff + mrow * 144 + aOff;
        uint32_t bBase = smem0 + stOff + A_BYTES + bOff;
#pragma unroll
        for (int s = 0; s < 4; s++) {          // 4 k16-slices in BK=64
            uint32_t a[4][4];
#pragma unroll
            for (int mi = 0; mi < 4; mi++)
                ldsm_x4(a[mi], aBase + mi * (16 * 144) + s * 32);
#pragma unroll
            for (int ni = 0; ni < 4; ni++) {
                uint32_t b1[2], b3[2];
                uint32_t ba = bBase + s * (16 * 272) + ni * 16;
                ldsm_x2t(b1, ba);
                ldsm_x2t(b3, ba + B1_BYTES);
#pragma unroll
                for (int mi = 0; mi < 4; mi++) {
                    mma_f16(accG[mi][ni], a[mi], b1[0], b1[1]);
                    mma_f16(accV[mi][ni], a[mi], b3[0], b3[1]);
                }
            }
        }
    }

    // epilogue: SwiGLU -> fp16 -> g_Hh
#pragma unroll
    for (int mi = 0; mi < 4; mi++) {
#pragma unroll
        for (int ni = 0; ni < 4; ni++) {
            int r = mrow + mi * 16 + grp;
            int c = ncol + ni * 8 + tig * 2;
            size_t gc = (size_t)ncol0 + c;
            const float* g = accG[mi][ni];
            const float* v = accV[mi][ni];
            if (r < rows) {
                float h0 = silu_f(g[0]) * v[0];
                float h1 = silu_f(g[1]) * v[1];
                *(__half2*)&g_Hh[(size_t)(row0 + r) * FF + gc] = __floats2half2_rn(h0, h1);
            }
            int r2 = r + 8;
            if (r2 < rows) {
                float h2 = silu_f(g[2]) * v[2];
                float h3 = silu_f(g[3]) * v[3];
                *(__half2*)&g_Hh[(size_t)(row0 + r2) * FF + gc] = __floats2half2_rn(h2, h3);
            }
        }
    }
}

// ---------------- launch #5: GEMM2 g_Hh @ w2 -> g_R ----------------
// 256 threads, 8 warps (2m x 4n), warp tile 64M x 64N; CTA 128M x 256N.
__device__ __forceinline__ void fill2(uint32_t sb, int kc, int ncol0,
                                      const __half* __restrict__ w2e,
                                      int row0, int rows, int tid) {
    int k0 = kc * 64;
#pragma unroll
    for (int i = 0; i < 4; i++) {
        int c = tid + i * 256;
        int r = c >> 3, c4 = c & 7;
        int rsrc = row0 + ((r < rows) ? r : 0);
        const __half* src = g_Hh + (size_t)rsrc * FF + k0 + c4 * 8;
        CP_ASYNC16(sb + r * 144 + c4 * 16, src);
    }
#pragma unroll
    for (int i = 0; i < 8; i++) {
        int c = tid + i * 256;
        int kr = c >> 5, n4 = c & 31;                    // 32 x 16B chunks per 256-half row
        const __half* src = w2e + (size_t)(k0 + kr) * DIM + ncol0 + n4 * 8;
        CP_ASYNC16(sb + A_BYTES + kr * 528 + n4 * 16, src);
    }
}

__global__ __launch_bounds__(256, 1)
void moe_gemm2(const __half* __restrict__ w2h) {
    int bid = blockIdx.x;
    int nt = bid & 3, mt = (bid >> 2) & 63, e = bid >> 8;
    int row0 = g_offsets[e] + mt * 128;
    int row_end = g_offsets[e + 1];
    if (row0 >= row_end) return;
    int rows = min(128, row_end - row0);

    extern __shared__ char dsm[];
    int tid = threadIdx.x;
    uint32_t smem0 = smem_u32(dsm);
    const __half* w2e = w2h + (size_t)e * FF * DIM;
    int ncol0 = nt * 256;

    int warp = tid >> 5, lane = tid & 31;
    int wm = warp & 1, wn = warp >> 1;
    int mrow = wm * 64, ncol = wn * 64;
    int grp = lane >> 2, tig = lane & 3;
    int lm = lane >> 3, lr = lane & 7;
    uint32_t aOff = (uint32_t)(((lm & 1) * 8 + lr) * 144 + (lm >> 1) * 16);
    uint32_t bOff = (uint32_t)(((lm & 1) * 8 + lr) * 528 + ncol * 2);

    float accC[4][8][4];
#pragma unroll
    for (int mi = 0; mi < 4; mi++)
#pragma unroll
        for (int ni = 0; ni < 8; ni++)
#pragma unroll
            for (int q = 0; q < 4; q++) accC[mi][ni][q] = 0.f;

    fill2(smem0 + 0 * STG2, 0, ncol0, w2e, row0, rows, tid); CP_COMMIT();
    fill2(smem0 + 1 * STG2, 1, ncol0, w2e, row0, rows, tid); CP_COMMIT();

    const int KT = FF / 64;   // 64
    for (int kt = 0; kt < KT; kt++) {
        CP_WAIT(1);
        __syncthreads();
        if (kt + 2 < KT)
            fill2(smem0 + ((kt + 2) % 3) * STG2, kt + 2, ncol0, w2e, row0, rows, tid);
        CP_COMMIT();

        uint32_t stOff = (uint32_t)((kt % 3) * STG2);
        uint32_t aBase = smem0 + stOff + mrow * 144 + aOff;
        uint32_t bBase = smem0 + stOff + A_BYTES + bOff;
#pragma unroll
        for (int s = 0; s < 4; s++) {
            uint32_t a[4][4];
#pragma unroll
            for (int mi = 0; mi < 4; mi++)
                ldsm_x4(a[mi], aBase + mi * (16 * 144) + s * 32);
#pragma unroll
            for (int ni = 0; ni < 8; ni++) {
                uint32_t b[2];
                ldsm_x2t(b, bBase + s * (16 * 528) + ni * 16);
#pragma unroll
                for (int mi = 0; mi < 4; mi++)
                    mma_f16(accC[mi][ni], a[mi], b[0], b[1]);
            }
        }
    }

    // epilogue: raw fp32 per-slot rows
#pragma unroll
    for (int mi = 0; mi < 4; mi++) {
#pragma unroll
        for (int ni = 0; ni < 8; ni++) {
            int r = mrow + mi * 16 + grp;
            int c = ncol + ni * 8 + tig * 2;
            size_t gc = (size_t)ncol0 + c;
            const float* a = accC[mi][ni];
            if (r < rows)
                *(float2*)&g_R[(size_t)(row0 + r) * DIM + gc] = make_float2(a[0], a[1]);
            int r2 = r + 8;
            if (r2 < rows)
                *(float2*)&g_R[(size_t)(row0 + r2) * DIM + gc] = make_float2(a[2], a[3]);
        }
    }
}

// ---------------- launch #6: combine out[t] = w0*R[s0] + w1*R[s1] ----------------
__global__ void moe_combine_kernel(float4* __restrict__ out4) {
    const int n = T_TOK * (DIM / 4);
    int i = blockIdx.x * blockDim.x + threadIdx.x;
    if (i >= n) return;
    int t = i >> 8;
    int c = i & 255;
    int s0 = g_slot[t * 2 + 0], s1 = g_slot[t * 2 + 1];
    float w0 = g_tok_w[t * 2 + 0], w1 = g_tok_w[t * 2 + 1];
    const float4* R4 = (const float4*)g_R;
    float4 a = R4[(size_t)s0 * 256 + c];
    float4 b = R4[(size_t)s1 * 256 + c];
    float4 o;
    o.x = w0 * a.x + w1 * b.x;
    o.y = w0 * a.y + w1 * b.y;
    o.z = w0 * a.z + w1 * b.z;
    o.w = w0 * a.w + w1 * b.w;
    out4[i] = o;
}

// ---------------- launch ----------------
extern "C" void kernel_launch(void* const* d_in, const int* in_sizes, int n_in,
                              void* d_out, int out_size) {
    (void)in_sizes; (void)n_in; (void)out_size;
    const float* x  = (const float*)d_in[0];
    const float* gw = (const float*)d_in[1];
    const float* w1 = (const float*)d_in[2];
    const float* w3 = (const float*)d_in[3];
    const float* w2 = (const float*)d_in[4];
    float* out = (float*)d_out;

    __half* d_w1h; cudaGetSymbolAddress((void**)&d_w1h, g_w1h);
    __half* d_w3h; cudaGetSymbolAddress((void**)&d_w3h, g_w3h);
    __half* d_w2h; cudaGetSymbolAddress((void**)&d_w2h, g_w2h);

    const int DYN1 = 3 * STG1;   // 159744
    const int DYN2 = 3 * STG2;   // 156672
    cudaFuncSetAttribute(moe_gemm1, cudaFuncAttributeMaxDynamicSharedMemorySize, DYN1);
    cudaFuncSetAttribute(moe_gemm2, cudaFuncAttributeMaxDynamicSharedMemorySize, DYN2);

    int nw = NE * DIM * FF / 4;
    // #1 weights fp32->fp16
    dim3 gw3((nw + 255) / 256, 3);
    moe_round_w<<<gw3, 256>>>((const float4*)w1, (__half2*)d_w1h,
                              (const float4*)w3, (__half2*)d_w3h,
                              (const float4*)w2, (__half2*)d_w2h, nw);
    // #2 gate + x convert (fused)
    moe_gate_kernel<<<T_TOK / 8, 256>>>(x, gw);
    // #3 count + offsets + scatter (fused, one block)
    moe_sched_kernel<<<1, 1024>>>();
    // #4 GEMM1: e(8) x nt(32) x mt(64), mt fastest  <- ncu profiles this launch
    moe_gemm1<<<8 * 32 * 64, 256, DYN1>>>(d_w1h, d_w3h);
    // #5 GEMM2: e(8) x mt(64) x nt(4), nt fastest
    moe_gemm2<<<8 * 64 * 4, 256, DYN2>>>(d_w2h);
    // #6 combine
    moe_combine_kernel<<<(T_TOK * DIM / 4 + 255) / 256, 256>>>((float4*)out);
}

// round 16
// speedup vs baseline: 1.7113x; 1.0153x over previous
#include <cuda_runtime.h>
#include <cuda_fp16.h>
#include <cstdint>
#include <math.h>

#define T_TOK 8192
#define DIM   1024
#define FF    4096
#define NE    8
#define SLOTS (T_TOK * 2)

// ---------------- device scratch ----------------
__device__ int    g_offsets[NE + 1];
__device__ int    g_tok_e[SLOTS];
__device__ float  g_tok_w[SLOTS];
__device__ int    g_tok[SLOTS];                   // slot -> token
__device__ int    g_slot[SLOTS];                  // token*2+k -> slot
__device__ __half g_Hh[(size_t)SLOTS * FF];       // SwiGLU intermediate (fp16)
__device__ float  g_R[(size_t)SLOTS * DIM];       // down-proj per slot (fp32)
__device__ __half g_xh[(size_t)T_TOK * DIM];      // fp16 x
__device__ __half g_w1h[(size_t)NE * DIM * FF];
__device__ __half g_w3h[(size_t)NE * DIM * FF];
__device__ __half g_w2h[(size_t)NE * FF * DIM];

// ---------------- helpers ----------------
__device__ __forceinline__ uint32_t smem_u32(const void* p) {
    uint32_t a;
    asm("{ .reg .u64 t; cvta.to.shared.u64 t, %1; cvt.u32.u64 %0, t; }" : "=r"(a) : "l"(p));
    return a;
}
#define CP_ASYNC16(dst, src) \
    asm volatile("cp.async.cg.shared.global [%0], [%1], 16;" :: "r"(dst), "l"(src) : "memory")
#define CP_COMMIT() asm volatile("cp.async.commit_group;" ::: "memory")
#define CP_WAIT(n)  asm volatile("cp.async.wait_group %0;" :: "n"(n) : "memory")

__device__ __forceinline__ void ldsm_x4(uint32_t* r, uint32_t addr) {
    asm volatile("ldmatrix.sync.aligned.m8n8.x4.shared.b16 {%0,%1,%2,%3}, [%4];"
        : "=r"(r[0]), "=r"(r[1]), "=r"(r[2]), "=r"(r[3]) : "r"(addr));
}
__device__ __forceinline__ void ldsm_x4t(uint32_t* r, uint32_t addr) {
    asm volatile("ldmatrix.sync.aligned.m8n8.x4.trans.shared.b16 {%0,%1,%2,%3}, [%4];"
        : "=r"(r[0]), "=r"(r[1]), "=r"(r[2]), "=r"(r[3]) : "r"(addr));
}
__device__ __forceinline__ void mma_f16(float* c, const uint32_t* a, uint32_t b0, uint32_t b1) {
    asm volatile(
        "mma.sync.aligned.m16n8k16.row.col.f32.f16.f16.f32 "
        "{%0,%1,%2,%3}, {%4,%5,%6,%7}, {%8,%9}, {%0,%1,%2,%3};\n"
        : "+f"(c[0]), "+f"(c[1]), "+f"(c[2]), "+f"(c[3])
        : "r"(a[0]), "r"(a[1]), "r"(a[2]), "r"(a[3]), "r"(b0), "r"(b1));
}
__device__ __forceinline__ float silu_f(float g) { return g / (1.0f + __expf(-g)); }

// ---------------- launch #1: convert 3 weight tensors fp32 -> fp16 ----------------
__global__ void moe_round_w(const float4* __restrict__ w1, __half2* __restrict__ d1,
                            const float4* __restrict__ w3, __half2* __restrict__ d3,
                            const float4* __restrict__ w2, __half2* __restrict__ d2, int n4) {
    const float4* s; __half2* d;
    if (blockIdx.y == 0)      { s = w1; d = d1; }
    else if (blockIdx.y == 1) { s = w3; d = d3; }
    else                      { s = w2; d = d2; }
    int i = blockIdx.x * blockDim.x + threadIdx.x;
    if (i >= n4) return;
    float4 v = s[i];
    d[(size_t)i * 2 + 0] = __floats2half2_rn(v.x, v.y);
    d[(size_t)i * 2 + 1] = __floats2half2_rn(v.z, v.w);
}

// ---------------- launch #2: gating + x fp16 conversion (fused) ----------------
__global__ void moe_gate_kernel(const float* __restrict__ x, const float* __restrict__ gw) {
    int warp = (blockIdx.x * blockDim.x + threadIdx.x) >> 5;
    int lane = threadIdx.x & 31;
    if (warp >= T_TOK) return;
    const float* xr = x + (size_t)warp * DIM;
    __half* xo = g_xh + (size_t)warp * DIM;
    float acc[NE];
#pragma unroll
    for (int e = 0; e < NE; e++) acc[e] = 0.f;
    for (int d = lane; d < DIM; d += 32) {
        float xv = xr[d];
        xo[d] = __float2half_rn(xv);
        const float* g = gw + d * NE;
#pragma unroll
        for (int e = 0; e < NE; e++) acc[e] += xv * g[e];
    }
#pragma unroll
    for (int e = 0; e < NE; e++)
#pragma unroll
        for (int o = 16; o > 0; o >>= 1) acc[e] += __shfl_xor_sync(0xffffffffu, acc[e], o);
    if (lane == 0) {
        int i1 = 0; float v1 = acc[0];
#pragma unroll
        for (int e = 1; e < NE; e++) if (acc[e] > v1) { v1 = acc[e]; i1 = e; }
        int i2 = -1; float v2 = -INFINITY;
#pragma unroll
        for (int e = 0; e < NE; e++) if (e != i1 && acc[e] > v2) { v2 = acc[e]; i2 = e; }
        float e2 = expf(v2 - v1);
        float inv = 1.0f / (1.0f + e2);
        g_tok_e[warp * 2 + 0] = i1;
        g_tok_e[warp * 2 + 1] = i2;
        g_tok_w[warp * 2 + 0] = inv;
        g_tok_w[warp * 2 + 1] = e2 * inv;
    }
}

// ---------------- launch #3: count + offsets + scatter (one block) ----------------
__global__ void moe_sched_kernel() {
    __shared__ int sc[NE];
    int tid = threadIdx.x;
    if (tid < NE) sc[tid] = 0;
    __syncthreads();
    for (int i = tid; i < SLOTS; i += blockDim.x)
        atomicAdd(&sc[g_tok_e[i]], 1);
    __syncthreads();
    if (tid == 0) {
        int o = 0;
        g_offsets[0] = 0;
#pragma unroll
        for (int e = 0; e < NE; e++) {
            int c = sc[e];
            o += c;
            g_offsets[e + 1] = o;
            sc[e] = o - c;
        }
    }
    __syncthreads();
    for (int i = tid; i < SLOTS; i += blockDim.x) {
        int e = g_tok_e[i];
        int slot = atomicAdd(&sc[e], 1);
        g_tok[slot] = i >> 1;
        g_slot[i] = slot;
    }
}

// ---------------- GEMM config (fp16, BK=64) ----------------
// A smem row: 64 halves + 8 pad = 144B. B1 row: 128 halves + 8 pad = 272B. B2 row: 256 + 8 pad = 528B.
#define A_BYTES  18432                    // 128 * 144
#define B1_BYTES 17408                    // 64 * 272
#define STG1     (A_BYTES + 2 * B1_BYTES) // 53248
#define B2_BYTES 33792                    // 64 * 528
#define STG2     (A_BYTES + B2_BYTES)     // 52224

// ---------------- launch #4: GEMM1 x@w1,x@w3 -> SwiGLU -> g_Hh ----------------
// 256 threads, 8 warps (2m x 4n), warp tile 64M x 32N per mat; CTA 128M x 128N/mat.
__device__ __forceinline__ void fill1(uint32_t sb, int kc, int ncol0,
                                      const __half* __restrict__ w1e,
                                      const __half* __restrict__ w3e,
                                      const int* sTok, int tid) {
    int k0 = kc * 64;
#pragma unroll
    for (int i = 0; i < 4; i++) {
        int c = tid + i * 256;
        int r = c >> 3, c4 = c & 7;
        const __half* src = g_xh + (size_t)sTok[r] * DIM + k0 + c4 * 8;
        CP_ASYNC16(sb + r * 144 + c4 * 16, src);
    }
    const __half* w = (tid < 128) ? w1e : w3e;
    uint32_t boff = sb + ((tid < 128) ? A_BYTES : (A_BYTES + B1_BYTES));
    int t = tid & 127;
#pragma unroll
    for (int i = 0; i < 8; i++) {
        int c = t + i * 128;
        int kr = c >> 4, n4 = c & 15;
        const __half* src = w + (size_t)(k0 + kr) * FF + ncol0 + n4 * 8;
        CP_ASYNC16(boff + kr * 272 + n4 * 16, src);
    }
}

__global__ __launch_bounds__(256, 1)
void moe_gemm1(const __half* __restrict__ w1h, const __half* __restrict__ w3h) {
    int bid = blockIdx.x;
    int mt = bid & 63, nt = (bid >> 6) & 31, e = bid >> 11;
    int row0 = g_offsets[e] + mt * 128;
    int row_end = g_offsets[e + 1];
    if (row0 >= row_end) return;
    int rows = min(128, row_end - row0);

    extern __shared__ char dsm[];
    __shared__ int sTok[128];

    int tid = threadIdx.x;
    if (tid < 128) sTok[tid] = g_tok[row0 + ((tid < rows) ? tid : 0)];
    __syncthreads();

    uint32_t smem0 = smem_u32(dsm);
    const __half* w1e = w1h + (size_t)e * DIM * FF;
    const __half* w3e = w3h + (size_t)e * DIM * FF;
    int ncol0 = nt * 128;

    int warp = tid >> 5, lane = tid & 31;
    int wm = warp & 1, wn = warp >> 1;
    int mrow = wm * 64, ncol = wn * 32;
    int grp = lane >> 2, tig = lane & 3;
    int lm = lane >> 3, lr = lane & 7;
    uint32_t aOff = (uint32_t)(((lm & 1) * 8 + lr) * 144 + (lm >> 1) * 16);
    // x4.trans B address: lanes 0-15 -> k-rows 0-15 at base col, lanes 16-31 -> same rows +8 cols
    uint32_t bOff = (uint32_t)(((lm & 1) * 8 + lr) * 272 + ncol * 2 + (lane >> 4) * 16);

    float accG[4][4][4], accV[4][4][4];
#pragma unroll
    for (int mi = 0; mi < 4; mi++)
#pragma unroll
        for (int ni = 0; ni < 4; ni++)
#pragma unroll
            for (int q = 0; q < 4; q++) { accG[mi][ni][q] = 0.f; accV[mi][ni][q] = 0.f; }

    fill1(smem0 + 0 * STG1, 0, ncol0, w1e, w3e, sTok, tid); CP_COMMIT();
    fill1(smem0 + 1 * STG1, 1, ncol0, w1e, w3e, sTok, tid); CP_COMMIT();

    const int KT = DIM / 64;   // 16
    for (int kt = 0; kt < KT; kt++) {
        CP_WAIT(1);
        __syncthreads();
        if (kt + 2 < KT)
            fill1(smem0 + ((kt + 2) % 3) * STG1, kt + 2, ncol0, w1e, w3e, sTok, tid);
        CP_COMMIT();

        uint32_t stOff = (uint32_t)((kt % 3) * STG1);
        uint32_t aB  = smem0 + stOff + mrow * 144 + aOff;
        uint32_t b1B = smem0 + stOff + A_BYTES + bOff;
        uint32_t b3B = b1B + B1_BYTES;

        uint32_t fa[2][4][4], f1[2][8], f3[2][8];
        // prologue: fragments for slice 0
#pragma unroll
        for (int mi = 0; mi < 4; mi++) ldsm_x4(fa[0][mi], aB + mi * (16 * 144));
        ldsm_x4t(&f1[0][0], b1B); ldsm_x4t(&f1[0][4], b1B + 32);
        ldsm_x4t(&f3[0][0], b3B); ldsm_x4t(&f3[0][4], b3B + 32);

#pragma unroll
        for (int s = 0; s < 4; s++) {          // 4 k16-slices in BK=64
            int cur = s & 1, nxt = cur ^ 1;
            if (s < 3) {                        // prefetch slice s+1 fragments
                uint32_t ao = aB + (s + 1) * 32;
#pragma unroll
                for (int mi = 0; mi < 4; mi++) ldsm_x4(fa[nxt][mi], ao + mi * (16 * 144));
                uint32_t bo1 = b1B + (s + 1) * (16 * 272);
                uint32_t bo3 = b3B + (s + 1) * (16 * 272);
                ldsm_x4t(&f1[nxt][0], bo1); ldsm_x4t(&f1[nxt][4], bo1 + 32);
                ldsm_x4t(&f3[nxt][0], bo3); ldsm_x4t(&f3[nxt][4], bo3 + 32);
            }
#pragma unroll
            for (int ni = 0; ni < 4; ni++) {
#pragma unroll
                for (int mi = 0; mi < 4; mi++) {
                    mma_f16(accG[mi][ni], fa[cur][mi], f1[cur][ni * 2], f1[cur][ni * 2 + 1]);
                    mma_f16(accV[mi][ni], fa[cur][mi], f3[cur][ni * 2], f3[cur][ni * 2 + 1]);
                }
            }
        }
    }

    // epilogue: SwiGLU -> fp16 -> g_Hh
#pragma unroll
    for (int mi = 0; mi < 4; mi++) {
#pragma unroll
        for (int ni = 0; ni < 4; ni++) {
            int r = mrow + mi * 16 + grp;
            int c = ncol + ni * 8 + tig * 2;
            size_t gc = (size_t)ncol0 + c;
            const float* g = accG[mi][ni];
            const float* v = accV[mi][ni];
            if (r < rows) {
                float h0 = silu_f(g[0]) * v[0];
                float h1 = silu_f(g[1]) * v[1];
                *(__half2*)&g_Hh[(size_t)(row0 + r) * FF + gc] = __floats2half2_rn(h0, h1);
            }
            int r2 = r + 8;
            if (r2 < rows) {
                float h2 = silu_f(g[2]) * v[2];
                float h3 = silu_f(g[3]) * v[3];
                *(__half2*)&g_Hh[(size_t)(row0 + r2) * FF + gc] = __floats2half2_rn(h2, h3);
            }
        }
    }
}

// ---------------- launch #5: GEMM2 g_Hh @ w2 -> g_R ----------------
// 256 threads, 8 warps (2m x 4n), warp tile 64M x 64N; CTA 128M x 256N.
__device__ __forceinline__ void fill2(uint32_t sb, int kc, int ncol0,
                                      const __half* __restrict__ w2e,
                                      int row0, int rows, int tid) {
    int k0 = kc * 64;
#pragma unroll
    for (int i = 0; i < 4; i++) {
        int c = tid + i * 256;
        int r = c >> 3, c4 = c & 7;
        int rsrc = row0 + ((r < rows) ? r : 0);
        const __half* src = g_Hh + (size_t)rsrc * FF + k0 + c4 * 8;
        CP_ASYNC16(sb + r * 144 + c4 * 16, src);
    }
#pragma unroll
    for (int i = 0; i < 8; i++) {
        int c = tid + i * 256;
        int kr = c >> 5, n4 = c & 31;
        const __half* src = w2e + (size_t)(k0 + kr) * DIM + ncol0 + n4 * 8;
        CP_ASYNC16(sb + A_BYTES + kr * 528 + n4 * 16, src);
    }
}

__global__ __launch_bounds__(256, 1)
void moe_gemm2(const __half* __restrict__ w2h) {
    int bid = blockIdx.x;
    int nt = bid & 3, mt = (bid >> 2) & 63, e = bid >> 8;
    int row0 = g_offsets[e] + mt * 128;
    int row_end = g_offsets[e + 1];
    if (row0 >= row_end) return;
    int rows = min(128, row_end - row0);

    extern __shared__ char dsm[];
    int tid = threadIdx.x;
    uint32_t smem0 = smem_u32(dsm);
    const __half* w2e = w2h + (size_t)e * FF * DIM;
    int ncol0 = nt * 256;

    int warp = tid >> 5, lane = tid & 31;
    int wm = warp & 1, wn = warp >> 1;
    int mrow = wm * 64, ncol = wn * 64;
    int grp = lane >> 2, tig = lane & 3;
    int lm = lane >> 3, lr = lane & 7;
    uint32_t aOff = (uint32_t)(((lm & 1) * 8 + lr) * 144 + (lm >> 1) * 16);
    uint32_t bOff = (uint32_t)(((lm & 1) * 8 + lr) * 528 + ncol * 2 + (lane >> 4) * 16);

    float accC[4][8][4];
#pragma unroll
    for (int mi = 0; mi < 4; mi++)
#pragma unroll
        for (int ni = 0; ni < 8; ni++)
#pragma unroll
            for (int q = 0; q < 4; q++) accC[mi][ni][q] = 0.f;

    fill2(smem0 + 0 * STG2, 0, ncol0, w2e, row0, rows, tid); CP_COMMIT();
    fill2(smem0 + 1 * STG2, 1, ncol0, w2e, row0, rows, tid); CP_COMMIT();

    const int KT = FF / 64;   // 64
    for (int kt = 0; kt < KT; kt++) {
        CP_WAIT(1);
        __syncthreads();
        if (kt + 2 < KT)
            fill2(smem0 + ((kt + 2) % 3) * STG2, kt + 2, ncol0, w2e, row0, rows, tid);
        CP_COMMIT();

        uint32_t stOff = (uint32_t)((kt % 3) * STG2);
        uint32_t aB = smem0 + stOff + mrow * 144 + aOff;
        uint32_t bB = smem0 + stOff + A_BYTES + bOff;

        uint32_t fa[2][4][4], fb[2][16];
        // prologue: fragments for slice 0
#pragma unroll
        for (int mi = 0; mi < 4; mi++) ldsm_x4(fa[0][mi], aB + mi * (16 * 144));
#pragma unroll
        for (int n4 = 0; n4 < 4; n4++) ldsm_x4t(&fb[0][n4 * 4], bB + n4 * 32);

#pragma unroll
        for (int s = 0; s < 4; s++) {
            int cur = s & 1, nxt = cur ^ 1;
            if (s < 3) {
                uint32_t ao = aB + (s + 1) * 32;
#pragma unroll
                for (int mi = 0; mi < 4; mi++) ldsm_x4(fa[nxt][mi], ao + mi * (16 * 144));
                uint32_t bo = bB + (s + 1) * (16 * 528);
#pragma unroll
                for (int n4 = 0; n4 < 4; n4++) ldsm_x4t(&fb[nxt][n4 * 4], bo + n4 * 32);
            }
#pragma unroll
            for (int ni = 0; ni < 8; ni++) {
#pragma unroll
                for (int mi = 0; mi < 4; mi++)
                    mma_f16(accC[mi][ni], fa[cur][mi], fb[cur][ni * 2], fb[cur][ni * 2 + 1]);
            }
        }
    }

    // epilogue: raw fp32 per-slot rows
#pragma unroll
    for (int mi = 0; mi < 4; mi++) {
#pragma unroll
        for (int ni = 0; ni < 8; ni++) {
            int r = mrow + mi * 16 + grp;
            int c = ncol + ni * 8 + tig * 2;
            size_t gc = (size_t)ncol0 + c;
            const float* a = accC[mi][ni];
            if (r < rows)
                *(float2*)&g_R[(size_t)(row0 + r) * DIM + gc] = make_float2(a[0], a[1]);
            int r2 = r + 8;
            if (r2 < rows)
                *(float2*)&g_R[(size_t)(row0 + r2) * DIM + gc] = make_float2(a[2], a[3]);
        }
    }
}

// ---------------- launch #6: combine out[t] = w0*R[s0] + w1*R[s1] ----------------
__global__ void moe_combine_kernel(float4* __restrict__ out4) {
    const int n = T_TOK * (DIM / 4);
    int i = blockIdx.x * blockDim.x + threadIdx.x;
    if (i >= n) return;
    int t = i >> 8;
    int c = i & 255;
    int s0 = g_slot[t * 2 + 0], s1 = g_slot[t * 2 + 1];
    float w0 = g_tok_w[t * 2 + 0], w1 = g_tok_w[t * 2 + 1];
    const float4* R4 = (const float4*)g_R;
    float4 a = R4[(size_t)s0 * 256 + c];
    float4 b = R4[(size_t)s1 * 256 + c];
    float4 o;
    o.x = w0 * a.x + w1 * b.x;
    o.y = w0 * a.y + w1 * b.y;
    o.z = w0 * a.z + w1 * b.z;
    o.w = w0 * a.w + w1 * b.w;
    out4[i] = o;
}

// ---------------- launch ----------------
extern "C" void kernel_launch(void* const* d_in, const int* in_sizes, int n_in,
                              void* d_out, int out_size) {
    (void)in_sizes; (void)n_in; (void)out_size;
    const float* x  = (const float*)d_in[0];
    const float* gw = (const float*)d_in[1];
    const float* w1 = (const float*)d_in[2];
    const float* w3 = (const float*)d_in[3];
    const float* w2 = (const float*)d_in[4];
    float* out = (float*)d_out;

    __half* d_w1h; cudaGetSymbolAddress((void**)&d_w1h, g_w1h);
    __half* d_w3h; cudaGetSymbolAddress((void**)&d_w3h, g_w3h);
    __half* d_w2h; cudaGetSymbolAddress((void**)&d_w2h, g_w2h);

    const int DYN1 = 3 * STG1;   // 159744
    const int DYN2 = 3 * STG2;   // 156672
    cudaFuncSetAttribute(moe_gemm1, cudaFuncAttributeMaxDynamicSharedMemorySize, DYN1);
    cudaFuncSetAttribute(moe_gemm2, cudaFuncAttributeMaxDynamicSharedMemorySize, DYN2);

    int nw = NE * DIM * FF / 4;
    // #1 weights fp32->fp16
    dim3 gw3((nw + 255) / 256, 3);
    moe_round_w<<<gw3, 256>>>((const float4*)w1, (__half2*)d_w1h,
                              (const float4*)w3, (__half2*)d_w3h,
                              (const float4*)w2, (__half2*)d_w2h, nw);
    // #2 gate + x convert (fused)
    moe_gate_kernel<<<T_TOK / 8, 256>>>(x, gw);
    // #3 count + offsets + scatter (fused, one block)
    moe_sched_kernel<<<1, 1024>>>();
    // #4 GEMM1: e(8) x nt(32) x mt(64), mt fastest  <- ncu profiles this launch
    moe_gemm1<<<8 * 32 * 64, 256, DYN1>>>(d_w1h, d_w3h);
    // #5 GEMM2: e(8) x mt(64) x nt(4), nt fastest
    moe_gemm2<<<8 * 64 * 4, 256, DYN2>>>(d_w2h);
    // #6 combine
    moe_combine_kernel<<<(T_TOK * DIM / 4 + 255) / 256, 256>>>((float4*)out);
}